// round 2
// baseline (speedup 1.0000x reference)
#include <cuda_runtime.h>
#include <cstddef>

#define N_NODES_MAX 100000
#define D_FEAT 128
#define HIDDEN 64

// Scratch: per-node precomputed table C[n][0:64]  = emb[n] @ w1[0:128]   + b1
//                                    C[n][64:128] = emb[n] @ w1[128:256]
__device__ float g_C[(size_t)N_NODES_MAX * 128];

// ---------------------------------------------------------------------------
// Kernel 1: C (M x 128) = A (M x 128) @ B (128 x 128), B assembled from w1.
//   B[k][j] = w1[k][j]            for j <  64
//   B[k][j] = w1[128+k][j-64]     for j >= 64
// Double-buffered smem-tiled SGEMM: BM=128, BN=128, BK=16,
// 256 threads, 8x8 register micro-tile per thread.
// ---------------------------------------------------------------------------
#define BM 128
#define BN 128
#define BK 16
#define APAD 136
#define BPAD 136

__global__ __launch_bounds__(256, 2)
void precompute_kernel(const float* __restrict__ A,
                       const float* __restrict__ w1,
                       const float* __restrict__ b1,
                       int M)
{
    __shared__ float As[2][BK][APAD];   // As[k][m]
    __shared__ float Bs[2][BK][BPAD];   // Bs[k][n]

    const int tid = threadIdx.x;
    const int bm  = blockIdx.x * BM;

    const int tx = tid & 15;   // n-tile coordinate (8 cols each)
    const int ty = tid >> 4;   // m-tile coordinate (8 rows each)

    float acc[8][8];
#pragma unroll
    for (int i = 0; i < 8; i++)
#pragma unroll
        for (int j = 0; j < 8; j++) acc[i][j] = 0.f;

    auto load_tiles = [&](int k0, int buf) {
        // A tile: 128 rows x 16 cols -> 512 float4, 2 per thread.
        #pragma unroll
        for (int i = 0; i < 2; i++) {
            int v   = tid + 256 * i;       // 0..511
            int row = v >> 2;              // 0..127
            int c4  = v & 3;               // float4 index within 16 cols
            int gr  = bm + row;
            if (gr >= M) gr = M - 1;       // clamp (stores are guarded)
            float4 a = *(const float4*)(A + (size_t)gr * D_FEAT + k0 + c4 * 4);
            As[buf][c4 * 4 + 0][row] = a.x;
            As[buf][c4 * 4 + 1][row] = a.y;
            As[buf][c4 * 4 + 2][row] = a.z;
            As[buf][c4 * 4 + 3][row] = a.w;
        }
        // B tile: 16 rows x 128 cols -> 512 float4, 2 per thread.
        #pragma unroll
        for (int i = 0; i < 2; i++) {
            int v   = tid + 256 * i;       // 0..511
            int k   = v >> 5;              // 0..15
            int seg = v & 31;              // float4 within the 128-wide row
            const float* src = (seg < 16)
                ? (w1 + (size_t)(k0 + k)       * HIDDEN + seg * 4)
                : (w1 + (size_t)(k0 + k + 128) * HIDDEN + (seg - 16) * 4);
            *(float4*)&Bs[buf][k][seg * 4] = *(const float4*)src;
        }
    };

    load_tiles(0, 0);
    __syncthreads();

    int buf = 0;
#pragma unroll 1
    for (int k0 = 0; k0 < D_FEAT; k0 += BK) {
        int nbuf = buf ^ 1;
        if (k0 + BK < D_FEAT) load_tiles(k0 + BK, nbuf);

#pragma unroll
        for (int k = 0; k < BK; k++) {
            float4 a0 = *(const float4*)&As[buf][k][ty * 8];
            float4 a1 = *(const float4*)&As[buf][k][ty * 8 + 4];
            float4 b0 = *(const float4*)&Bs[buf][k][tx * 8];
            float4 b1v = *(const float4*)&Bs[buf][k][tx * 8 + 4];
            float a[8] = {a0.x, a0.y, a0.z, a0.w, a1.x, a1.y, a1.z, a1.w};
            float b[8] = {b0.x, b0.y, b0.z, b0.w, b1v.x, b1v.y, b1v.z, b1v.w};
#pragma unroll
            for (int i = 0; i < 8; i++)
#pragma unroll
                for (int j = 0; j < 8; j++)
                    acc[i][j] = fmaf(a[i], b[j], acc[i][j]);
        }
        __syncthreads();
        buf = nbuf;
    }

    // Epilogue: fold b1 into columns 0..63 (tx < 8), store 8x8 block.
    float bias[8];
#pragma unroll
    for (int j = 0; j < 8; j++)
        bias[j] = (tx < 8) ? b1[tx * 8 + j] : 0.f;

#pragma unroll
    for (int i = 0; i < 8; i++) {
        int gm = bm + ty * 8 + i;
        if (gm < M) {
            float4 o0, o1;
            o0.x = acc[i][0] + bias[0]; o0.y = acc[i][1] + bias[1];
            o0.z = acc[i][2] + bias[2]; o0.w = acc[i][3] + bias[3];
            o1.x = acc[i][4] + bias[4]; o1.y = acc[i][5] + bias[5];
            o1.z = acc[i][6] + bias[6]; o1.w = acc[i][7] + bias[7];
            *(float4*)(g_C + (size_t)gm * 128 + tx * 8)     = o0;
            *(float4*)(g_C + (size_t)gm * 128 + tx * 8 + 4) = o1;
        }
    }
}

// ---------------------------------------------------------------------------
// Kernel 2: per-edge readout. out[e] = sum_j relu(C[s][j] + C[d][64+j]) * w2[j]
// One thread per edge; C is L2-resident (51.2 MB < L2).
//
// Index dtype is detected on-device: the reference asks for int64 but JAX
// without x64 silently emits int32. Interpreting the buffer as u32 words,
// int64 (values < 2^17) => every odd word is 0. We sample 16 odd words once
// per block; deterministic for fixed input, graph-safe, no extra launches.
// ---------------------------------------------------------------------------
__global__ __launch_bounds__(256)
void edge_kernel(const unsigned int* __restrict__ ts_raw,
                 const float* __restrict__ w2,
                 float* __restrict__ out, int E, int M)
{
    __shared__ float w2s[HIDDEN];
    __shared__ int is64;
    if (threadIdx.x < HIDDEN) w2s[threadIdx.x] = w2[threadIdx.x];
    if (threadIdx.x == 0) {
        // Buffer has 2*E values => >= 2*E u32 words in either dtype.
        // Check odd words 1,3,...,31 (all within bounds: E >= 16).
        unsigned int acc = 0;
        #pragma unroll
        for (int i = 1; i < 32; i += 2) acc |= ts_raw[i];
        is64 = (acc == 0) ? 1 : 0;
    }
    __syncthreads();

    int e = blockIdx.x * blockDim.x + threadIdx.x;
    if (e >= E) return;

    unsigned int s, d;
    if (is64) {
        s = ts_raw[4 * (size_t)e];          // low word of int64 src
        d = ts_raw[4 * (size_t)e + 2];      // low word of int64 dst
    } else {
        s = ts_raw[2 * (size_t)e];
        d = ts_raw[2 * (size_t)e + 1];
    }
    // Safety clamp (no-op for valid data; prevents crash on contract surprise)
    if (s >= (unsigned)M) s = 0;
    if (d >= (unsigned)M) d = 0;

    const float4* P = (const float4*)(g_C + (size_t)s * 128);        // src half
    const float4* Q = (const float4*)(g_C + (size_t)d * 128 + 64);   // dst half

    float acc = 0.f;
#pragma unroll
    for (int i = 0; i < 16; i++) {
        float4 p = P[i];
        float4 q = Q[i];
        float4 w = *(const float4*)&w2s[i * 4];
        acc = fmaf(fmaxf(p.x + q.x, 0.f), w.x, acc);
        acc = fmaf(fmaxf(p.y + q.y, 0.f), w.y, acc);
        acc = fmaf(fmaxf(p.z + q.z, 0.f), w.z, acc);
        acc = fmaf(fmaxf(p.w + q.w, 0.f), w.w, acc);
    }
    out[e] = acc;
}

// ---------------------------------------------------------------------------
extern "C" void kernel_launch(void* const* d_in, const int* in_sizes, int n_in,
                              void* d_out, int out_size)
{
    const float*        emb = (const float*)d_in[0];        // (N_NODES, 128) f32
    const unsigned int* ts  = (const unsigned int*)d_in[1]; // (N_EDGES, 2) i32 or i64
    const float*        w1  = (const float*)d_in[2];        // (256, 64) f32
    const float*        b1  = (const float*)d_in[3];        // (64,) f32
    const float*        w2  = (const float*)d_in[4];        // (64, 1) f32
    float*              out = (float*)d_out;                // (N_EDGES, 1) f32

    int M = in_sizes[0] / D_FEAT;   // number of nodes
    int E = in_sizes[1] / 2;        // number of edges

    precompute_kernel<<<(M + BM - 1) / BM, 256>>>(emb, w1, b1, M);
    edge_kernel<<<(E + 255) / 256, 256>>>(ts, w2, out, E, M);
}

// round 4
// speedup vs baseline: 1.4839x; 1.4839x over previous
#include <cuda_runtime.h>
#include <cuda_bf16.h>
#include <cstdint>
#include <cstddef>

#define N_NODES_MAX 100000
#define D_FEAT 128
#define HIDDEN 64

__device__ float g_C[(size_t)N_NODES_MAX * 128];

// ===========================================================================
// PTX helpers — sm_80-era (compile under plain sm_100 target)
// ===========================================================================
__device__ __forceinline__ uint32_t smem_u32(const void* p) {
    uint32_t a;
    asm("{ .reg .u64 t; cvta.to.shared.u64 t, %1; cvt.u32.u64 %0, t; }"
        : "=r"(a) : "l"(p));
    return a;
}
__device__ __forceinline__ void ldsm_x4(uint32_t* r, uint32_t addr) {
    asm volatile("ldmatrix.sync.aligned.m8n8.x4.shared.b16 {%0,%1,%2,%3}, [%4];"
                 : "=r"(r[0]), "=r"(r[1]), "=r"(r[2]), "=r"(r[3]) : "r"(addr));
}
__device__ __forceinline__ void ldsm_x2(uint32_t* r, uint32_t addr) {
    asm volatile("ldmatrix.sync.aligned.m8n8.x2.shared.b16 {%0,%1}, [%2];"
                 : "=r"(r[0]), "=r"(r[1]) : "r"(addr));
}
__device__ __forceinline__ void mma_bf16(float* c, const uint32_t* a, const uint32_t* b) {
    asm volatile("mma.sync.aligned.m16n8k16.row.col.f32.bf16.bf16.f32 "
                 "{%0,%1,%2,%3}, {%4,%5,%6,%7}, {%8,%9}, {%0,%1,%2,%3};"
                 : "+f"(c[0]), "+f"(c[1]), "+f"(c[2]), "+f"(c[3])
                 : "r"(a[0]), "r"(a[1]), "r"(a[2]), "r"(a[3]),
                   "r"(b[0]), "r"(b[1]));
}
__device__ __forceinline__ uint32_t packbf2(float x, float y) {
    __nv_bfloat162 t = __floats2bfloat162_rn(x, y);
    return *(uint32_t*)&t;
}

// ===========================================================================
// Kernel 1: C (M x 128) = A (M x 128) @ W (128 x 128) via split-bf16 mma.sync.
//   W[n][k] = n<64 ? w1[k][n] : w1[128+k][n-64]   (W stored n-major, k contig)
//   D = Ah·Wh + Al·Wh + Ah·Wl  (fp32 accumulate)  -> + b1 on cols 0..63
// CTA: 256 threads = 8 warps (2x4), warp tile m64 x n32, full K=128.
// ===========================================================================
#define SA 136                       // smem row stride in bf16 units (272 B)
#define SM_AH 0
#define SM_AL (SM_AH + 128 * SA * 2)   // 34816
#define SM_BH (SM_AL + 128 * SA * 2)
#define SM_BL (SM_BH + 128 * SA * 2)
#define SM_B1 (SM_BL + 128 * SA * 2)
#define SMEM_GEMM_TOTAL (SM_B1 + 64 * 4)

__global__ __launch_bounds__(256, 1)
void precompute_kernel(const float* __restrict__ A,
                       const float* __restrict__ w1,
                       const float* __restrict__ b1,
                       int M)
{
    extern __shared__ char smem[];
    const uint32_t sb  = smem_u32(smem);
    const int tid  = threadIdx.x;
    const int wid  = tid >> 5;
    const int lane = tid & 31;
    const int bm   = blockIdx.x * 128;

    float* b1s = (float*)(smem + SM_B1);
    if (tid < 64) b1s[tid] = b1[tid];

    // ---- Stage A tile: 128 rows x 128 cols f32 -> bf16 hi/lo ----
#pragma unroll
    for (int i = 0; i < 16; i++) {
        int idx4 = tid + i * 256;            // 0..4095
        int row  = idx4 >> 5;                // 0..127
        int col  = (idx4 & 31) * 4;          // 0..124
        int gr   = bm + row; if (gr >= M) gr = M - 1;
        float4 v = *(const float4*)(A + (size_t)gr * D_FEAT + col);
        float h0 = __bfloat162float(__float2bfloat16(v.x));
        float h1 = __bfloat162float(__float2bfloat16(v.y));
        float h2 = __bfloat162float(__float2bfloat16(v.z));
        float h3 = __bfloat162float(__float2bfloat16(v.w));
        uint32_t off = ((uint32_t)row * SA + col) * 2;   // bytes
        *(uint32_t*)(smem + SM_AH + off)     = packbf2(v.x, v.y);
        *(uint32_t*)(smem + SM_AH + off + 4) = packbf2(v.z, v.w);
        *(uint32_t*)(smem + SM_AL + off)     = packbf2(v.x - h0, v.y - h1);
        *(uint32_t*)(smem + SM_AL + off + 4) = packbf2(v.z - h2, v.w - h3);
    }

    // ---- Stage W tile: read w1 (256x64) coalesced, scatter to [n][k] ----
#pragma unroll
    for (int i = 0; i < 16; i++) {
        int idx4  = tid + i * 256;           // 0..4095
        int w1row = idx4 >> 4;               // 0..255
        int n0    = (idx4 & 15) * 4;         // 0..60
        float4 v  = *(const float4*)(w1 + (size_t)w1row * HIDDEN + n0);
        int k     = (w1row < 128) ? w1row : (w1row - 128);
        int nb    = (w1row < 128) ? 0 : 64;
        float vv[4] = {v.x, v.y, v.z, v.w};
#pragma unroll
        for (int j = 0; j < 4; j++) {
            int n = nb + n0 + j;
            float hi = __bfloat162float(__float2bfloat16(vv[j]));
            uint32_t off = ((uint32_t)n * SA + k) * 2;
            *(__nv_bfloat16*)(smem + SM_BH + off) = __float2bfloat16(vv[j]);
            *(__nv_bfloat16*)(smem + SM_BL + off) = __float2bfloat16(vv[j] - hi);
        }
    }
    __syncthreads();

    // ---- Warp tiles: 2 (m) x 4 (n); each warp m64 x n32 ----
    const int wm = wid >> 2;            // 0..1
    const int wn = wid & 3;             // 0..3
    const int m_base = wm * 64;
    const int n_base = wn * 32;

    // ldmatrix per-lane row offsets (bytes)
    const int rA  = (lane & 7) + ((lane >> 3) & 1) * 8;   // 0..15
    const int kA8 = ((lane >> 4) & 1) * 8;
    const uint32_t aoff = ((uint32_t)(m_base + rA) * SA + kA8) * 2;
    const int rB  = lane & 7;
    const int kB8 = ((lane >> 3) & 1) * 8;
    const uint32_t boff = ((uint32_t)(n_base + rB) * SA + kB8) * 2;

    float acc[4][4][4];
#pragma unroll
    for (int mt = 0; mt < 4; mt++)
#pragma unroll
        for (int nt = 0; nt < 4; nt++)
#pragma unroll
            for (int r = 0; r < 4; r++) acc[mt][nt][r] = 0.f;

#pragma unroll
    for (int s = 0; s < 8; s++) {
        const uint32_t k0b = (uint32_t)(s * 16) * 2;      // byte offset along k
        uint32_t ah[4][4], al[4][4], bh[4][2], bl[4][2];
#pragma unroll
        for (int mt = 0; mt < 4; mt++) {
            uint32_t ao = aoff + (uint32_t)(mt * 16 * SA) * 2 + k0b;
            ldsm_x4(ah[mt], sb + SM_AH + ao);
            ldsm_x4(al[mt], sb + SM_AL + ao);
        }
#pragma unroll
        for (int nt = 0; nt < 4; nt++) {
            uint32_t bo = boff + (uint32_t)(nt * 8 * SA) * 2 + k0b;
            ldsm_x2(bh[nt], sb + SM_BH + bo);
            ldsm_x2(bl[nt], sb + SM_BL + bo);
        }
#pragma unroll
        for (int mt = 0; mt < 4; mt++)
#pragma unroll
            for (int nt = 0; nt < 4; nt++) {
                mma_bf16(acc[mt][nt], ah[mt], bh[nt]);
                mma_bf16(acc[mt][nt], al[mt], bh[nt]);
                mma_bf16(acc[mt][nt], ah[mt], bl[nt]);
            }
    }

    // ---- Epilogue: regs -> g_C, bias on cols < 64 ----
    const int er = lane >> 2;           // 0..7
    const int ec = (lane & 3) * 2;      // 0,2,4,6
#pragma unroll
    for (int mt = 0; mt < 4; mt++) {
#pragma unroll
        for (int half = 0; half < 2; half++) {
            int gm = bm + m_base + mt * 16 + er + half * 8;
            if (gm >= M) continue;
            float* dst = g_C + (size_t)gm * 128;
#pragma unroll
            for (int nt = 0; nt < 4; nt++) {
                int col = n_base + nt * 8 + ec;
                float2 o;
                o.x = acc[mt][nt][half * 2 + 0];
                o.y = acc[mt][nt][half * 2 + 1];
                if (col < 64) { o.x += b1s[col]; o.y += b1s[col + 1]; }
                *(float2*)(dst + col) = o;
            }
        }
    }
}

// ===========================================================================
// Kernel 2: per-edge readout, 8 threads per edge (coalesced row-half loads).
// out[e] = sum_j relu(C[s][j] + C[d][64+j]) * w2[j]
// ===========================================================================
__global__ __launch_bounds__(256)
void edge_kernel(const unsigned int* __restrict__ ts_raw,
                 const float* __restrict__ w2,
                 float* __restrict__ out, int E, int M)
{
    __shared__ float w2s[HIDDEN];
    __shared__ int is64;
    if (threadIdx.x < HIDDEN) w2s[threadIdx.x] = w2[threadIdx.x];
    if (threadIdx.x == 0) {
        // int64 indices < 2^17 => every odd u32 word is 0 (little-endian).
        unsigned int acc = 0;
#pragma unroll
        for (int i = 1; i < 32; i += 2) acc |= ts_raw[i];
        is64 = (acc == 0) ? 1 : 0;
    }
    __syncthreads();

    const int tid = threadIdx.x;
    const int sub = tid & 7;
    int e = blockIdx.x * 32 + (tid >> 3);
    if (e >= E) return;

    unsigned int s, d;
    if (sub == 0) {
        if (is64) {
            s = ts_raw[4 * (size_t)e];
            d = ts_raw[4 * (size_t)e + 2];
        } else {
            s = ts_raw[2 * (size_t)e];
            d = ts_raw[2 * (size_t)e + 1];
        }
        if (s >= (unsigned)M) s = 0;
        if (d >= (unsigned)M) d = 0;
    }
    s = __shfl_sync(0xffffffffu, s, 0, 8);
    d = __shfl_sync(0xffffffffu, d, 0, 8);

    const float4* P = (const float4*)(g_C + (size_t)s * 128) + sub * 2;
    const float4* Q = (const float4*)(g_C + (size_t)d * 128 + 64) + sub * 2;
    const float4* W = (const float4*)w2s + sub * 2;

    float acc = 0.f;
#pragma unroll
    for (int i = 0; i < 2; i++) {
        float4 p = P[i], q = Q[i], w = W[i];
        acc = fmaf(fmaxf(p.x + q.x, 0.f), w.x, acc);
        acc = fmaf(fmaxf(p.y + q.y, 0.f), w.y, acc);
        acc = fmaf(fmaxf(p.z + q.z, 0.f), w.z, acc);
        acc = fmaf(fmaxf(p.w + q.w, 0.f), w.w, acc);
    }
    acc += __shfl_down_sync(0xffffffffu, acc, 4, 8);
    acc += __shfl_down_sync(0xffffffffu, acc, 2, 8);
    acc += __shfl_down_sync(0xffffffffu, acc, 1, 8);
    if (sub == 0) out[e] = acc;
}

// ===========================================================================
extern "C" void kernel_launch(void* const* d_in, const int* in_sizes, int n_in,
                              void* d_out, int out_size)
{
    const float*        emb = (const float*)d_in[0];
    const unsigned int* ts  = (const unsigned int*)d_in[1];
    const float*        w1  = (const float*)d_in[2];
    const float*        b1  = (const float*)d_in[3];
    const float*        w2  = (const float*)d_in[4];
    float*              out = (float*)d_out;

    int M = in_sizes[0] / D_FEAT;
    int E = in_sizes[1] / 2;

    cudaFuncSetAttribute(precompute_kernel,
                         cudaFuncAttributeMaxDynamicSharedMemorySize, SMEM_GEMM_TOTAL);
    precompute_kernel<<<(M + 127) / 128, 256, SMEM_GEMM_TOTAL>>>(emb, w1, b1, M);
    edge_kernel<<<(E + 31) / 32, 256>>>(ts, w2, out, E, M);
}

// round 6
// speedup vs baseline: 2.3750x; 1.6005x over previous
#include <cuda_runtime.h>
#include <cuda_bf16.h>
#include <cuda_fp16.h>
#include <cstdint>
#include <cstddef>

#define N_NODES_MAX 100000
#define D_FEAT 128
#define HIDDEN 64
#define SA 136   // smem/global W row stride in bf16 units (272 B)

// fp16 node table: C[n][0:64] = emb@w1_top + b1 ; C[n][64:128] = emb@w1_bot
__device__ __align__(16) __half g_C[(size_t)N_NODES_MAX * 128];
// Pre-converted W (bf16 hi|lo), [2][128 n][SA k] — exact smem image
__device__ __align__(16) __nv_bfloat16 g_W[2 * 128 * SA];

// ===========================================================================
// PTX helpers (sm_80-era; compile under plain sm_100 target)
// ===========================================================================
__device__ __forceinline__ uint32_t smem_u32(const void* p) {
    uint32_t a;
    asm("{ .reg .u64 t; cvta.to.shared.u64 t, %1; cvt.u32.u64 %0, t; }"
        : "=r"(a) : "l"(p));
    return a;
}
__device__ __forceinline__ void ldsm_x4(uint32_t* r, uint32_t addr) {
    asm volatile("ldmatrix.sync.aligned.m8n8.x4.shared.b16 {%0,%1,%2,%3}, [%4];"
                 : "=r"(r[0]), "=r"(r[1]), "=r"(r[2]), "=r"(r[3]) : "r"(addr));
}
__device__ __forceinline__ void ldsm_x2(uint32_t* r, uint32_t addr) {
    asm volatile("ldmatrix.sync.aligned.m8n8.x2.shared.b16 {%0,%1}, [%2];"
                 : "=r"(r[0]), "=r"(r[1]) : "r"(addr));
}
__device__ __forceinline__ void mma_bf16(float* c, const uint32_t* a, const uint32_t* b) {
    asm volatile("mma.sync.aligned.m16n8k16.row.col.f32.bf16.bf16.f32 "
                 "{%0,%1,%2,%3}, {%4,%5,%6,%7}, {%8,%9}, {%0,%1,%2,%3};"
                 : "+f"(c[0]), "+f"(c[1]), "+f"(c[2]), "+f"(c[3])
                 : "r"(a[0]), "r"(a[1]), "r"(a[2]), "r"(a[3]),
                   "r"(b[0]), "r"(b[1]));
}
__device__ __forceinline__ void cp_async16(uint32_t dst, const void* src) {
    asm volatile("cp.async.cg.shared.global [%0], [%1], 16;"
                 :: "r"(dst), "l"(src) : "memory");
}
__device__ __forceinline__ uint32_t packbf2(float x, float y) {
    __nv_bfloat162 t = __floats2bfloat162_rn(x, y);
    return *(uint32_t*)&t;
}

// ===========================================================================
// Kernel 0: convert w1 -> g_W (bf16 hi/lo), layout [n][k], k contiguous.
//   W[n][k] = n<64 ? w1[k*64+n] : w1[(128+k)*64 + (n-64)]
// ===========================================================================
__global__ void setup_w_kernel(const float* __restrict__ w1)
{
    int idx = blockIdx.x * blockDim.x + threadIdx.x;   // 0..16383
    if (idx >= 128 * 128) return;
    int k = idx >> 7;
    int n = idx & 127;
    float v = (n < 64) ? w1[(size_t)k * HIDDEN + n]
                       : w1[(size_t)(128 + k) * HIDDEN + (n - 64)];
    __nv_bfloat16 hi = __float2bfloat16(v);
    g_W[n * SA + k]            = hi;
    g_W[128 * SA + n * SA + k] = __float2bfloat16(v - __bfloat162float(hi));
}

// ===========================================================================
// Kernel 1: C (M x 128) = A (M x 128) @ W (128 x 128), split-bf16 mma.sync.
//   D = Ah·Wh + Al·Wh + Ah·Wl (fp32 acc) -> +b1 (cols<64) -> fp16 store
// CTA: BM=64, 256 threads = 8 warps (2x4), warp tile m32 x n32, full K=128.
// smem 104.7 KB -> 2 CTAs/SM.
// ===========================================================================
#define SM_AH 0
#define SM_AL 17408
#define SM_WH 34816
#define SM_WL 69632
#define SM_B1 104448
#define SMEM_GEMM_TOTAL (SM_B1 + 64 * 4)

__global__ __launch_bounds__(256, 2)
void precompute_kernel(const float* __restrict__ A,
                       const float* __restrict__ b1,
                       int M)
{
    extern __shared__ char smem[];
    const uint32_t sb  = smem_u32(smem);
    const int tid  = threadIdx.x;
    const int wid  = tid >> 5;
    const int lane = tid & 31;
    const int bm   = blockIdx.x * 64;

    // ---- W hi/lo: flat async copy of the pre-built image (69,632 B) ----
    {
        const uint4* src = (const uint4*)g_W;
#pragma unroll
        for (int i = 0; i < 17; i++) {
            int v = tid + i * 256;               // 0..4351
            cp_async16(sb + SM_WH + v * 16, src + v);
        }
        asm volatile("cp.async.commit_group;" ::: "memory");
    }

    float* b1s = (float*)(smem + SM_B1);
    if (tid < 64) b1s[tid] = b1[tid];

    // ---- A tile: 64 rows x 128 cols f32 -> bf16 hi/lo (fused conversion) ----
#pragma unroll
    for (int i = 0; i < 8; i++) {
        int idx4 = tid + i * 256;                // 0..2047
        int row  = idx4 >> 5;                    // 0..63
        int col  = (idx4 & 31) * 4;              // 0..124
        int gr   = bm + row; if (gr >= M) gr = M - 1;
        float4 v = *(const float4*)(A + (size_t)gr * D_FEAT + col);
        float h0 = __bfloat162float(__float2bfloat16(v.x));
        float h1 = __bfloat162float(__float2bfloat16(v.y));
        float h2 = __bfloat162float(__float2bfloat16(v.z));
        float h3 = __bfloat162float(__float2bfloat16(v.w));
        uint32_t off = ((uint32_t)row * SA + col) * 2;
        *(uint32_t*)(smem + SM_AH + off)     = packbf2(v.x, v.y);
        *(uint32_t*)(smem + SM_AH + off + 4) = packbf2(v.z, v.w);
        *(uint32_t*)(smem + SM_AL + off)     = packbf2(v.x - h0, v.y - h1);
        *(uint32_t*)(smem + SM_AL + off + 4) = packbf2(v.z - h2, v.w - h3);
    }
    asm volatile("cp.async.wait_group 0;" ::: "memory");
    __syncthreads();

    // ---- Warp tiles: 2 (m) x 4 (n); each warp m32 x n32 ----
    const int wm = wid >> 2;            // 0..1
    const int wn = wid & 3;             // 0..3
    const int m_base = wm * 32;
    const int n_base = wn * 32;

    const int rA  = (lane & 7) + ((lane >> 3) & 1) * 8;
    const int kA8 = ((lane >> 4) & 1) * 8;
    const uint32_t aoff = ((uint32_t)(m_base + rA) * SA + kA8) * 2;
    const int rB  = lane & 7;
    const int kB8 = ((lane >> 3) & 1) * 8;
    const uint32_t boff = ((uint32_t)(n_base + rB) * SA + kB8) * 2;

    float acc[2][4][4];
#pragma unroll
    for (int mt = 0; mt < 2; mt++)
#pragma unroll
        for (int nt = 0; nt < 4; nt++)
#pragma unroll
            for (int r = 0; r < 4; r++) acc[mt][nt][r] = 0.f;

#pragma unroll
    for (int s = 0; s < 8; s++) {
        const uint32_t k0b = (uint32_t)(s * 16) * 2;
        uint32_t ah[2][4], al[2][4], bh[4][2], bl[4][2];
#pragma unroll
        for (int mt = 0; mt < 2; mt++) {
            uint32_t ao = aoff + (uint32_t)(mt * 16 * SA) * 2 + k0b;
            ldsm_x4(ah[mt], sb + SM_AH + ao);
            ldsm_x4(al[mt], sb + SM_AL + ao);
        }
#pragma unroll
        for (int nt = 0; nt < 4; nt++) {
            uint32_t bo = boff + (uint32_t)(nt * 8 * SA) * 2 + k0b;
            ldsm_x2(bh[nt], sb + SM_WH + bo);
            ldsm_x2(bl[nt], sb + SM_WL + bo);
        }
#pragma unroll
        for (int mt = 0; mt < 2; mt++)
#pragma unroll
            for (int nt = 0; nt < 4; nt++) {
                mma_bf16(acc[mt][nt], ah[mt], bh[nt]);
                mma_bf16(acc[mt][nt], al[mt], bh[nt]);
                mma_bf16(acc[mt][nt], ah[mt], bl[nt]);
            }
    }

    // ---- Epilogue: +bias (cols<64), convert fp16, store half2 ----
    const int er = lane >> 2;
    const int ec = (lane & 3) * 2;
#pragma unroll
    for (int mt = 0; mt < 2; mt++) {
#pragma unroll
        for (int half = 0; half < 2; half++) {
            int gm = bm + m_base + mt * 16 + er + half * 8;
            if (gm >= M) continue;
            __half* dst = g_C + (size_t)gm * 128;
#pragma unroll
            for (int nt = 0; nt < 4; nt++) {
                int col = n_base + nt * 8 + ec;
                float x = acc[mt][nt][half * 2 + 0];
                float y = acc[mt][nt][half * 2 + 1];
                if (col < 64) { x += b1s[col]; y += b1s[col + 1]; }
                *(__half2*)(dst + col) = __floats2half2_rn(x, y);
            }
        }
    }
}

// ===========================================================================
// Kernel 2: per-edge readout, 8 threads/edge, fp16 C (1 uint4 per half-row).
// out[e] = sum_j relu(C[s][j] + C[d][64+j]) * w2[j]
// ===========================================================================
__global__ __launch_bounds__(256)
void edge_kernel(const unsigned int* __restrict__ ts_raw,
                 const float* __restrict__ w2,
                 float* __restrict__ out, int E, int M)
{
    __shared__ float w2s[HIDDEN];
    __shared__ int is64;
    if (threadIdx.x < HIDDEN) w2s[threadIdx.x] = w2[threadIdx.x];
    if (threadIdx.x == 0) {
        // int64 indices < 2^17 => every odd u32 word is 0 (little-endian)
        unsigned int acc = 0;
#pragma unroll
        for (int i = 1; i < 32; i += 2) acc |= ts_raw[i];
        is64 = (acc == 0) ? 1 : 0;
    }
    __syncthreads();

    const int tid = threadIdx.x;
    const int sub = tid & 7;
    int e = blockIdx.x * 32 + (tid >> 3);
    if (e >= E) return;

    unsigned int s, d;
    if (sub == 0) {
        if (is64) {
            s = ts_raw[4 * (size_t)e];
            d = ts_raw[4 * (size_t)e + 2];
        } else {
            s = ts_raw[2 * (size_t)e];
            d = ts_raw[2 * (size_t)e + 1];
        }
        if (s >= (unsigned)M) s = 0;
        if (d >= (unsigned)M) d = 0;
    }
    s = __shfl_sync(0xffffffffu, s, 0, 8);
    d = __shfl_sync(0xffffffffu, d, 0, 8);

    // lane handles features [sub*8, sub*8+8): one uint4 (8 halves) per side
    uint4 p = *((const uint4*)(g_C + (size_t)s * 128) + sub);
    uint4 q = *((const uint4*)(g_C + (size_t)d * 128 + 64) + sub);
    float4 w0 = ((const float4*)w2s)[sub * 2];
    float4 w1v = ((const float4*)w2s)[sub * 2 + 1];
    const float wv[8] = {w0.x, w0.y, w0.z, w0.w, w1v.x, w1v.y, w1v.z, w1v.w};

    const __half2* ph = (const __half2*)&p;
    const __half2* qh = (const __half2*)&q;
    float acc = 0.f;
#pragma unroll
    for (int i = 0; i < 4; i++) {
        float2 a = __half22float2(ph[i]);
        float2 b = __half22float2(qh[i]);
        acc = fmaf(fmaxf(a.x + b.x, 0.f), wv[i * 2 + 0], acc);
        acc = fmaf(fmaxf(a.y + b.y, 0.f), wv[i * 2 + 1], acc);
    }
    acc += __shfl_down_sync(0xffffffffu, acc, 4, 8);
    acc += __shfl_down_sync(0xffffffffu, acc, 2, 8);
    acc += __shfl_down_sync(0xffffffffu, acc, 1, 8);
    if (sub == 0) out[e] = acc;
}

// ===========================================================================
extern "C" void kernel_launch(void* const* d_in, const int* in_sizes, int n_in,
                              void* d_out, int out_size)
{
    const float*        emb = (const float*)d_in[0];
    const unsigned int* ts  = (const unsigned int*)d_in[1];
    const float*        w1  = (const float*)d_in[2];
    const float*        b1  = (const float*)d_in[3];
    const float*        w2  = (const float*)d_in[4];
    float*              out = (float*)d_out;

    int M = in_sizes[0] / D_FEAT;
    int E = in_sizes[1] / 2;

    setup_w_kernel<<<64, 256>>>(w1);
    cudaFuncSetAttribute(precompute_kernel,
                         cudaFuncAttributeMaxDynamicSharedMemorySize, SMEM_GEMM_TOTAL);
    precompute_kernel<<<(M + 63) / 64, 256, SMEM_GEMM_TOTAL>>>(emb, b1, M);
    edge_kernel<<<(E + 31) / 32, 256>>>(ts, w2, out, E, M);
}

// round 7
// speedup vs baseline: 3.3903x; 1.4275x over previous
#include <cuda_runtime.h>
#include <cuda_fp16.h>
#include <cstdint>
#include <cstddef>

#define N_NODES_MAX 100000
#define D_FEAT 128
#define HIDDEN 64
#define SA 136   // smem/global W row stride in fp16 units (272 B)

// fp16 node table: C[n][0:64] = emb@w1_top + b1 ; C[n][64:128] = emb@w1_bot
__device__ __align__(16) __half g_C[(size_t)N_NODES_MAX * 128];
// Pre-converted W (fp16), [128 n][SA k] — exact smem image
__device__ __align__(16) __half g_W[128 * SA];

// ===========================================================================
// PTX helpers (sm_80-era; compile under plain sm_100 target)
// ===========================================================================
__device__ __forceinline__ uint32_t smem_u32(const void* p) {
    uint32_t a;
    asm("{ .reg .u64 t; cvta.to.shared.u64 t, %1; cvt.u32.u64 %0, t; }"
        : "=r"(a) : "l"(p));
    return a;
}
__device__ __forceinline__ void ldsm_x4(uint32_t* r, uint32_t addr) {
    asm volatile("ldmatrix.sync.aligned.m8n8.x4.shared.b16 {%0,%1,%2,%3}, [%4];"
                 : "=r"(r[0]), "=r"(r[1]), "=r"(r[2]), "=r"(r[3]) : "r"(addr));
}
__device__ __forceinline__ void ldsm_x2(uint32_t* r, uint32_t addr) {
    asm volatile("ldmatrix.sync.aligned.m8n8.x2.shared.b16 {%0,%1}, [%2];"
                 : "=r"(r[0]), "=r"(r[1]) : "r"(addr));
}
__device__ __forceinline__ void mma_fp16(float* c, const uint32_t* a, const uint32_t* b) {
    asm volatile("mma.sync.aligned.m16n8k16.row.col.f32.f16.f16.f32 "
                 "{%0,%1,%2,%3}, {%4,%5,%6,%7}, {%8,%9}, {%0,%1,%2,%3};"
                 : "+f"(c[0]), "+f"(c[1]), "+f"(c[2]), "+f"(c[3])
                 : "r"(a[0]), "r"(a[1]), "r"(a[2]), "r"(a[3]),
                   "r"(b[0]), "r"(b[1]));
}
__device__ __forceinline__ void cp_async16(uint32_t dst, const void* src) {
    asm volatile("cp.async.cg.shared.global [%0], [%1], 16;"
                 :: "r"(dst), "l"(src) : "memory");
}
__device__ __forceinline__ uint32_t packh2(float x, float y) {
    __half2 t = __floats2half2_rn(x, y);
    return *(uint32_t*)&t;
}

// ===========================================================================
// Kernel 0: convert w1 -> g_W (fp16), layout [n][k], k contiguous.
//   W[n][k] = n<64 ? w1[k*64+n] : w1[(128+k)*64 + (n-64)]
// ===========================================================================
__global__ void setup_w_kernel(const float* __restrict__ w1)
{
    int idx = blockIdx.x * blockDim.x + threadIdx.x;   // 0..16383
    if (idx >= 128 * 128) return;
    int k = idx >> 7;
    int n = idx & 127;
    float v = (n < 64) ? w1[(size_t)k * HIDDEN + n]
                       : w1[(size_t)(128 + k) * HIDDEN + (n - 64)];
    g_W[n * SA + k] = __float2half_rn(v);
}

// ===========================================================================
// Kernel 1: C (M x 128) = A (M x 128) @ W (128 x 128), single fp16 mma.sync
// (fp32 accumulate) -> +b1 (cols<64) -> fp16 store.
// CTA: BM=64, 256 threads = 8 warps (2x4), warp tile m32 x n32, full K=128.
// smem ~52.7 KB -> 4 CTAs/SM.
// ===========================================================================
#define SM_AH 0
#define SM_WH 17408
#define SM_B1 52224
#define SMEM_GEMM_TOTAL (SM_B1 + 64 * 4)

__global__ __launch_bounds__(256, 4)
void precompute_kernel(const float* __restrict__ A,
                       const float* __restrict__ b1,
                       int M)
{
    extern __shared__ char smem[];
    const uint32_t sb  = smem_u32(smem);
    const int tid  = threadIdx.x;
    const int wid  = tid >> 5;
    const int lane = tid & 31;
    const int bm   = blockIdx.x * 64;

    // ---- W: flat async copy of the pre-built fp16 image (34,816 B) ----
    {
        const uint4* src = (const uint4*)g_W;
#pragma unroll
        for (int i = 0; i < 9; i++) {
            int v = tid + i * 256;               // 0..2303
            if (v < 2176) cp_async16(sb + SM_WH + v * 16, src + v);
        }
        asm volatile("cp.async.commit_group;" ::: "memory");
    }

    float* b1s = (float*)(smem + SM_B1);
    if (tid < 64) b1s[tid] = b1[tid];

    // ---- A tile: 64 rows x 128 cols f32 -> fp16 ----
#pragma unroll
    for (int i = 0; i < 8; i++) {
        int idx4 = tid + i * 256;                // 0..2047
        int row  = idx4 >> 5;                    // 0..63
        int col  = (idx4 & 31) * 4;              // 0..124
        int gr   = bm + row; if (gr >= M) gr = M - 1;
        float4 v = *(const float4*)(A + (size_t)gr * D_FEAT + col);
        uint32_t off = ((uint32_t)row * SA + col) * 2;
        *(uint32_t*)(smem + SM_AH + off)     = packh2(v.x, v.y);
        *(uint32_t*)(smem + SM_AH + off + 4) = packh2(v.z, v.w);
    }
    asm volatile("cp.async.wait_group 0;" ::: "memory");
    __syncthreads();

    // ---- Warp tiles: 2 (m) x 4 (n); each warp m32 x n32 ----
    const int wm = wid >> 2;            // 0..1
    const int wn = wid & 3;             // 0..3
    const int m_base = wm * 32;
    const int n_base = wn * 32;

    const int rA  = (lane & 7) + ((lane >> 3) & 1) * 8;
    const int kA8 = ((lane >> 4) & 1) * 8;
    const uint32_t aoff = ((uint32_t)(m_base + rA) * SA + kA8) * 2;
    const int rB  = lane & 7;
    const int kB8 = ((lane >> 3) & 1) * 8;
    const uint32_t boff = ((uint32_t)(n_base + rB) * SA + kB8) * 2;

    float acc[2][4][4];
#pragma unroll
    for (int mt = 0; mt < 2; mt++)
#pragma unroll
        for (int nt = 0; nt < 4; nt++)
#pragma unroll
            for (int r = 0; r < 4; r++) acc[mt][nt][r] = 0.f;

#pragma unroll
    for (int s = 0; s < 8; s++) {
        const uint32_t k0b = (uint32_t)(s * 16) * 2;
        uint32_t ah[2][4], bh[4][2];
#pragma unroll
        for (int mt = 0; mt < 2; mt++)
            ldsm_x4(ah[mt], sb + SM_AH + aoff + (uint32_t)(mt * 16 * SA) * 2 + k0b);
#pragma unroll
        for (int nt = 0; nt < 4; nt++)
            ldsm_x2(bh[nt], sb + SM_WH + boff + (uint32_t)(nt * 8 * SA) * 2 + k0b);
#pragma unroll
        for (int mt = 0; mt < 2; mt++)
#pragma unroll
            for (int nt = 0; nt < 4; nt++)
                mma_fp16(acc[mt][nt], ah[mt], bh[nt]);
    }

    // ---- Epilogue: +bias (cols<64), convert fp16, store half2 ----
    const int er = lane >> 2;
    const int ec = (lane & 3) * 2;
#pragma unroll
    for (int mt = 0; mt < 2; mt++) {
#pragma unroll
        for (int half = 0; half < 2; half++) {
            int gm = bm + m_base + mt * 16 + er + half * 8;
            if (gm >= M) continue;
            __half* dst = g_C + (size_t)gm * 128;
#pragma unroll
            for (int nt = 0; nt < 4; nt++) {
                int col = n_base + nt * 8 + ec;
                float x = acc[mt][nt][half * 2 + 0];
                float y = acc[mt][nt][half * 2 + 1];
                if (col < 64) { x += b1s[col]; y += b1s[col + 1]; }
                *(__half2*)(dst + col) = __floats2half2_rn(x, y);
            }
        }
    }
}

// ===========================================================================
// Kernel 2: per-edge readout, 8 threads/edge, fp16 C (1 uint4 per half-row).
// out[e] = sum_j relu(C[s][j] + C[d][64+j]) * w2[j]
// ===========================================================================
__global__ __launch_bounds__(256)
void edge_kernel(const unsigned int* __restrict__ ts_raw,
                 const float* __restrict__ w2,
                 float* __restrict__ out, int E, int M)
{
    __shared__ float w2s[HIDDEN];
    __shared__ int is64;
    if (threadIdx.x < HIDDEN) w2s[threadIdx.x] = w2[threadIdx.x];
    if (threadIdx.x == 0) {
        // int64 indices < 2^17 => every odd u32 word is 0 (little-endian)
        unsigned int acc = 0;
#pragma unroll
        for (int i = 1; i < 32; i += 2) acc |= ts_raw[i];
        is64 = (acc == 0) ? 1 : 0;
    }
    __syncthreads();

    const int tid = threadIdx.x;
    const int sub = tid & 7;
    int e = blockIdx.x * 32 + (tid >> 3);
    if (e >= E) return;

    unsigned int s, d;
    if (sub == 0) {
        if (is64) {
            s = ts_raw[4 * (size_t)e];
            d = ts_raw[4 * (size_t)e + 2];
        } else {
            s = ts_raw[2 * (size_t)e];
            d = ts_raw[2 * (size_t)e + 1];
        }
        if (s >= (unsigned)M) s = 0;
        if (d >= (unsigned)M) d = 0;
    }
    s = __shfl_sync(0xffffffffu, s, 0, 8);
    d = __shfl_sync(0xffffffffu, d, 0, 8);

    // lane handles features [sub*8, sub*8+8): one uint4 (8 halves) per side
    uint4 p = *((const uint4*)(g_C + (size_t)s * 128) + sub);
    uint4 q = *((const uint4*)(g_C + (size_t)d * 128 + 64) + sub);
    float4 w0 = ((const float4*)w2s)[sub * 2];
    float4 w1v = ((const float4*)w2s)[sub * 2 + 1];
    const float wv[8] = {w0.x, w0.y, w0.z, w0.w, w1v.x, w1v.y, w1v.z, w1v.w};

    const __half2* ph = (const __half2*)&p;
    const __half2* qh = (const __half2*)&q;
    float acc = 0.f;
#pragma unroll
    for (int i = 0; i < 4; i++) {
        float2 a = __half22float2(ph[i]);
        float2 b = __half22float2(qh[i]);
        acc = fmaf(fmaxf(a.x + b.x, 0.f), wv[i * 2 + 0], acc);
        acc = fmaf(fmaxf(a.y + b.y, 0.f), wv[i * 2 + 1], acc);
    }
    acc += __shfl_down_sync(0xffffffffu, acc, 4, 8);
    acc += __shfl_down_sync(0xffffffffu, acc, 2, 8);
    acc += __shfl_down_sync(0xffffffffu, acc, 1, 8);
    if (sub == 0) out[e] = acc;
}

// ===========================================================================
extern "C" void kernel_launch(void* const* d_in, const int* in_sizes, int n_in,
                              void* d_out, int out_size)
{
    const float*        emb = (const float*)d_in[0];
    const unsigned int* ts  = (const unsigned int*)d_in[1];
    const float*        w1  = (const float*)d_in[2];
    const float*        b1  = (const float*)d_in[3];
    const float*        w2  = (const float*)d_in[4];
    float*              out = (float*)d_out;

    int M = in_sizes[0] / D_FEAT;
    int E = in_sizes[1] / 2;

    setup_w_kernel<<<64, 256>>>(w1);
    cudaFuncSetAttribute(precompute_kernel,
                         cudaFuncAttributeMaxDynamicSharedMemorySize, SMEM_GEMM_TOTAL);
    precompute_kernel<<<(M + 63) / 64, 256, SMEM_GEMM_TOTAL>>>(emb, b1, M);
    edge_kernel<<<(E + 31) / 32, 256>>>(ts, w2, out, E, M);
}

// round 8
// speedup vs baseline: 3.9481x; 1.1645x over previous
#include <cuda_runtime.h>
#include <cuda_fp16.h>
#include <cstdint>
#include <cstddef>

#define N_NODES_MAX 100000
#define D_FEAT 128
#define HIDDEN 64
#define SA 136   // smem/global W row stride in fp16 units (272 B)

// fp16 node table: C[n][0:64] = emb@w1_top + b1 ; C[n][64:128] = emb@w1_bot
__device__ __align__(16) __half g_C[(size_t)N_NODES_MAX * 128];
// Pre-converted W (fp16), [128 n][SA k] — exact smem image
__device__ __align__(16) __half g_W[128 * SA];

// ===========================================================================
// PTX helpers (sm_80-era; compile under plain sm_100 target)
// ===========================================================================
__device__ __forceinline__ uint32_t smem_u32(const void* p) {
    uint32_t a;
    asm("{ .reg .u64 t; cvta.to.shared.u64 t, %1; cvt.u32.u64 %0, t; }"
        : "=r"(a) : "l"(p));
    return a;
}
__device__ __forceinline__ void ldsm_x4(uint32_t* r, uint32_t addr) {
    asm volatile("ldmatrix.sync.aligned.m8n8.x4.shared.b16 {%0,%1,%2,%3}, [%4];"
                 : "=r"(r[0]), "=r"(r[1]), "=r"(r[2]), "=r"(r[3]) : "r"(addr));
}
__device__ __forceinline__ void ldsm_x2(uint32_t* r, uint32_t addr) {
    asm volatile("ldmatrix.sync.aligned.m8n8.x2.shared.b16 {%0,%1}, [%2];"
                 : "=r"(r[0]), "=r"(r[1]) : "r"(addr));
}
__device__ __forceinline__ void mma_fp16(float* c, const uint32_t* a, const uint32_t* b) {
    asm volatile("mma.sync.aligned.m16n8k16.row.col.f32.f16.f16.f32 "
                 "{%0,%1,%2,%3}, {%4,%5,%6,%7}, {%8,%9}, {%0,%1,%2,%3};"
                 : "+f"(c[0]), "+f"(c[1]), "+f"(c[2]), "+f"(c[3])
                 : "r"(a[0]), "r"(a[1]), "r"(a[2]), "r"(a[3]),
                   "r"(b[0]), "r"(b[1]));
}
__device__ __forceinline__ void cp_async16(uint32_t dst, const void* src) {
    asm volatile("cp.async.cg.shared.global [%0], [%1], 16;"
                 :: "r"(dst), "l"(src) : "memory");
}
__device__ __forceinline__ uint32_t packh2(float x, float y) {
    __half2 t = __floats2half2_rn(x, y);
    return *(uint32_t*)&t;
}

// ===========================================================================
// Kernel 0: convert w1 -> g_W (fp16), layout [n][k], k contiguous.
//   W[n][k] = n<64 ? w1[k*64+n] : w1[(128+k)*64 + (n-64)]
// ===========================================================================
__global__ void setup_w_kernel(const float* __restrict__ w1)
{
    int idx = blockIdx.x * blockDim.x + threadIdx.x;   // 0..16383
    if (idx >= 128 * 128) return;
    int k = idx >> 7;
    int n = idx & 127;
    float v = (n < 64) ? w1[(size_t)k * HIDDEN + n]
                       : w1[(size_t)(128 + k) * HIDDEN + (n - 64)];
    g_W[n * SA + k] = __float2half_rn(v);
}

// ===========================================================================
// Kernel 1: C (M x 128) = A (M x 128) @ W (128 x 128), single fp16 mma.sync
// (fp32 accumulate) -> +b1 (cols<64) -> fp16 store.
// CTA: BM=64, 256 threads = 8 warps (2x4), warp tile m32 x n32, full K=128.
// smem ~52.7 KB; occ 3 (85 regs/thread — 32 acc + operands fit w/o spills).
// ===========================================================================
#define SM_AH 0
#define SM_WH 17408
#define SM_B1 52224
#define SMEM_GEMM_TOTAL (SM_B1 + 64 * 4)

__global__ __launch_bounds__(256, 3)
void precompute_kernel(const float* __restrict__ A,
                       const float* __restrict__ b1,
                       int M)
{
    extern __shared__ char smem[];
    const uint32_t sb  = smem_u32(smem);
    const int tid  = threadIdx.x;
    const int wid  = tid >> 5;
    const int lane = tid & 31;
    const int bm   = blockIdx.x * 64;

    // ---- W: flat async copy of the pre-built fp16 image (34,816 B) ----
    {
        const uint4* src = (const uint4*)g_W;
#pragma unroll
        for (int i = 0; i < 9; i++) {
            int v = tid + i * 256;               // 0..2303
            if (v < 2176) cp_async16(sb + SM_WH + v * 16, src + v);
        }
        asm volatile("cp.async.commit_group;" ::: "memory");
    }

    float* b1s = (float*)(smem + SM_B1);
    if (tid < 64) b1s[tid] = b1[tid];

    // ---- A tile: 64 rows x 128 cols f32 -> fp16 ----
#pragma unroll
    for (int i = 0; i < 8; i++) {
        int idx4 = tid + i * 256;                // 0..2047
        int row  = idx4 >> 5;                    // 0..63
        int col  = (idx4 & 31) * 4;              // 0..124
        int gr   = bm + row; if (gr >= M) gr = M - 1;
        float4 v = *(const float4*)(A + (size_t)gr * D_FEAT + col);
        uint32_t off = ((uint32_t)row * SA + col) * 2;
        *(uint32_t*)(smem + SM_AH + off)     = packh2(v.x, v.y);
        *(uint32_t*)(smem + SM_AH + off + 4) = packh2(v.z, v.w);
    }
    asm volatile("cp.async.wait_group 0;" ::: "memory");
    __syncthreads();

    // ---- Warp tiles: 2 (m) x 4 (n); each warp m32 x n32 ----
    const int wm = wid >> 2;            // 0..1
    const int wn = wid & 3;             // 0..3
    const int m_base = wm * 32;
    const int n_base = wn * 32;

    const int rA  = (lane & 7) + ((lane >> 3) & 1) * 8;
    const int kA8 = ((lane >> 4) & 1) * 8;
    const uint32_t aoff = ((uint32_t)(m_base + rA) * SA + kA8) * 2;
    const int rB  = lane & 7;
    const int kB8 = ((lane >> 3) & 1) * 8;
    const uint32_t boff = ((uint32_t)(n_base + rB) * SA + kB8) * 2;

    float acc[2][4][4];
#pragma unroll
    for (int mt = 0; mt < 2; mt++)
#pragma unroll
        for (int nt = 0; nt < 4; nt++)
#pragma unroll
            for (int r = 0; r < 4; r++) acc[mt][nt][r] = 0.f;

#pragma unroll
    for (int s = 0; s < 8; s++) {
        const uint32_t k0b = (uint32_t)(s * 16) * 2;
        uint32_t ah[2][4], bh[4][2];
#pragma unroll
        for (int mt = 0; mt < 2; mt++)
            ldsm_x4(ah[mt], sb + SM_AH + aoff + (uint32_t)(mt * 16 * SA) * 2 + k0b);
#pragma unroll
        for (int nt = 0; nt < 4; nt++)
            ldsm_x2(bh[nt], sb + SM_WH + boff + (uint32_t)(nt * 8 * SA) * 2 + k0b);
#pragma unroll
        for (int mt = 0; mt < 2; mt++)
#pragma unroll
            for (int nt = 0; nt < 4; nt++)
                mma_fp16(acc[mt][nt], ah[mt], bh[nt]);
    }

    // ---- Epilogue: +bias (cols<64), convert fp16, store half2 ----
    const int er = lane >> 2;
    const int ec = (lane & 3) * 2;
#pragma unroll
    for (int mt = 0; mt < 2; mt++) {
#pragma unroll
        for (int half = 0; half < 2; half++) {
            int gm = bm + m_base + mt * 16 + er + half * 8;
            if (gm >= M) continue;
            __half* dst = g_C + (size_t)gm * 128;
#pragma unroll
            for (int nt = 0; nt < 4; nt++) {
                int col = n_base + nt * 8 + ec;
                float x = acc[mt][nt][half * 2 + 0];
                float y = acc[mt][nt][half * 2 + 1];
                if (col < 64) { x += b1s[col]; y += b1s[col + 1]; }
                *(__half2*)(dst + col) = __floats2half2_rn(x, y);
            }
        }
    }
}

// ===========================================================================
// Kernel 2: per-edge readout, 8 threads/edge, 2 edges per thread-group
// (4 independent gathers in flight per thread -> 2x MLP, latency-bound fix).
// out[e] = sum_j relu(C[s][j] + C[d][64+j]) * w2[j]
// ===========================================================================
__global__ __launch_bounds__(256)
void edge_kernel(const unsigned int* __restrict__ ts_raw,
                 const float* __restrict__ w2,
                 float* __restrict__ out, int E, int M)
{
    __shared__ float w2s[HIDDEN];
    __shared__ int is64;
    if (threadIdx.x < HIDDEN) w2s[threadIdx.x] = w2[threadIdx.x];
    if (threadIdx.x == 0) {
        // int64 indices < 2^17 => every odd u32 word is 0 (little-endian)
        unsigned int acc = 0;
#pragma unroll
        for (int i = 1; i < 32; i += 2) acc |= ts_raw[i];
        is64 = (acc == 0) ? 1 : 0;
    }
    __syncthreads();

    const int tid = threadIdx.x;
    const int sub = tid & 7;
    const int grp = tid >> 3;                       // 0..31
    int e0 = blockIdx.x * 64 + grp;                 // first edge
    int e1 = e0 + 32;                               // second edge

    // fetch both index pairs on the sub==0 lane, broadcast
    unsigned int s0 = 0, d0 = 0, s1 = 0, d1 = 0;
    if (sub == 0) {
        if (is64) {
            if (e0 < E) { s0 = ts_raw[4 * (size_t)e0]; d0 = ts_raw[4 * (size_t)e0 + 2]; }
            if (e1 < E) { s1 = ts_raw[4 * (size_t)e1]; d1 = ts_raw[4 * (size_t)e1 + 2]; }
        } else {
            if (e0 < E) { s0 = ts_raw[2 * (size_t)e0]; d0 = ts_raw[2 * (size_t)e0 + 1]; }
            if (e1 < E) { s1 = ts_raw[2 * (size_t)e1]; d1 = ts_raw[2 * (size_t)e1 + 1]; }
        }
        if (s0 >= (unsigned)M) s0 = 0;
        if (d0 >= (unsigned)M) d0 = 0;
        if (s1 >= (unsigned)M) s1 = 0;
        if (d1 >= (unsigned)M) d1 = 0;
    }
    s0 = __shfl_sync(0xffffffffu, s0, 0, 8);
    d0 = __shfl_sync(0xffffffffu, d0, 0, 8);
    s1 = __shfl_sync(0xffffffffu, s1, 0, 8);
    d1 = __shfl_sync(0xffffffffu, d1, 0, 8);

    // 4 independent 16B gathers in flight
    uint4 p0 = *((const uint4*)(g_C + (size_t)s0 * 128) + sub);
    uint4 q0 = *((const uint4*)(g_C + (size_t)d0 * 128 + 64) + sub);
    uint4 p1 = *((const uint4*)(g_C + (size_t)s1 * 128) + sub);
    uint4 q1 = *((const uint4*)(g_C + (size_t)d1 * 128 + 64) + sub);

    float4 w0 = ((const float4*)w2s)[sub * 2];
    float4 w1v = ((const float4*)w2s)[sub * 2 + 1];
    const float wv[8] = {w0.x, w0.y, w0.z, w0.w, w1v.x, w1v.y, w1v.z, w1v.w};

    const __half2* ph0 = (const __half2*)&p0;
    const __half2* qh0 = (const __half2*)&q0;
    const __half2* ph1 = (const __half2*)&p1;
    const __half2* qh1 = (const __half2*)&q1;
    float acc0 = 0.f, acc1 = 0.f;
#pragma unroll
    for (int i = 0; i < 4; i++) {
        float2 a0 = __half22float2(ph0[i]);
        float2 b0v = __half22float2(qh0[i]);
        acc0 = fmaf(fmaxf(a0.x + b0v.x, 0.f), wv[i * 2 + 0], acc0);
        acc0 = fmaf(fmaxf(a0.y + b0v.y, 0.f), wv[i * 2 + 1], acc0);
        float2 a1 = __half22float2(ph1[i]);
        float2 b1v = __half22float2(qh1[i]);
        acc1 = fmaf(fmaxf(a1.x + b1v.x, 0.f), wv[i * 2 + 0], acc1);
        acc1 = fmaf(fmaxf(a1.y + b1v.y, 0.f), wv[i * 2 + 1], acc1);
    }
#pragma unroll
    for (int off = 4; off >= 1; off >>= 1) {
        acc0 += __shfl_down_sync(0xffffffffu, acc0, off, 8);
        acc1 += __shfl_down_sync(0xffffffffu, acc1, off, 8);
    }
    if (sub == 0) {
        if (e0 < E) out[e0] = acc0;
        if (e1 < E) out[e1] = acc1;
    }
}

// ===========================================================================
extern "C" void kernel_launch(void* const* d_in, const int* in_sizes, int n_in,
                              void* d_out, int out_size)
{
    const float*        emb = (const float*)d_in[0];
    const unsigned int* ts  = (const unsigned int*)d_in[1];
    const float*        w1  = (const float*)d_in[2];
    const float*        b1  = (const float*)d_in[3];
    const float*        w2  = (const float*)d_in[4];
    float*              out = (float*)d_out;

    int M = in_sizes[0] / D_FEAT;
    int E = in_sizes[1] / 2;

    setup_w_kernel<<<64, 256>>>(w1);
    cudaFuncSetAttribute(precompute_kernel,
                         cudaFuncAttributeMaxDynamicSharedMemorySize, SMEM_GEMM_TOTAL);
    precompute_kernel<<<(M + 63) / 64, 256, SMEM_GEMM_TOTAL>>>(emb, b1, M);
    edge_kernel<<<(E + 63) / 64, 256>>>(ts, w2, out, E, M);
}

// round 10
// speedup vs baseline: 3.9515x; 1.0009x over previous
#include <cuda_runtime.h>
#include <cuda_fp16.h>
#include <cstdint>
#include <cstddef>

#define N_NODES_MAX 100000
#define D_FEAT 128
#define HIDDEN 64
#define SA 136   // smem/global W row stride in fp16 units (272 B)

// fp16 node table: C[n][0:64] = emb@w1_top + b1 ; C[n][64:128] = emb@w1_bot
__device__ __align__(16) __half g_C[(size_t)N_NODES_MAX * 128];
// Pre-converted W (fp16), [128 n][SA k] — exact smem image
__device__ __align__(16) __half g_W[128 * SA];

// ===========================================================================
// PTX helpers (sm_80-era; compile under plain sm_100 target)
// ===========================================================================
__device__ __forceinline__ uint32_t smem_u32(const void* p) {
    uint32_t a;
    asm("{ .reg .u64 t; cvta.to.shared.u64 t, %1; cvt.u32.u64 %0, t; }"
        : "=r"(a) : "l"(p));
    return a;
}
__device__ __forceinline__ void ldsm_x4(uint32_t* r, uint32_t addr) {
    asm volatile("ldmatrix.sync.aligned.m8n8.x4.shared.b16 {%0,%1,%2,%3}, [%4];"
                 : "=r"(r[0]), "=r"(r[1]), "=r"(r[2]), "=r"(r[3]) : "r"(addr));
}
__device__ __forceinline__ void ldsm_x2(uint32_t* r, uint32_t addr) {
    asm volatile("ldmatrix.sync.aligned.m8n8.x2.shared.b16 {%0,%1}, [%2];"
                 : "=r"(r[0]), "=r"(r[1]) : "r"(addr));
}
__device__ __forceinline__ void mma_fp16(float* c, const uint32_t* a, const uint32_t* b) {
    asm volatile("mma.sync.aligned.m16n8k16.row.col.f32.f16.f16.f32 "
                 "{%0,%1,%2,%3}, {%4,%5,%6,%7}, {%8,%9}, {%0,%1,%2,%3};"
                 : "+f"(c[0]), "+f"(c[1]), "+f"(c[2]), "+f"(c[3])
                 : "r"(a[0]), "r"(a[1]), "r"(a[2]), "r"(a[3]),
                   "r"(b[0]), "r"(b[1]));
}
__device__ __forceinline__ void cp_async16(uint32_t dst, const void* src) {
    asm volatile("cp.async.cg.shared.global [%0], [%1], 16;"
                 :: "r"(dst), "l"(src) : "memory");
}
__device__ __forceinline__ uint32_t packh2(float x, float y) {
    __half2 t = __floats2half2_rn(x, y);
    return *(uint32_t*)&t;
}

// ===========================================================================
// Kernel 0: convert w1 -> g_W (fp16), layout [n][k], k contiguous.
//   W[n][k] = n<64 ? w1[k*64+n] : w1[(128+k)*64 + (n-64)]
// ===========================================================================
__global__ void setup_w_kernel(const float* __restrict__ w1)
{
    int idx = blockIdx.x * blockDim.x + threadIdx.x;   // 0..16383
    if (idx >= 128 * 128) return;
    int k = idx >> 7;
    int n = idx & 127;
    float v = (n < 64) ? w1[(size_t)k * HIDDEN + n]
                       : w1[(size_t)(128 + k) * HIDDEN + (n - 64)];
    g_W[n * SA + k] = __float2half_rn(v);
}

// ===========================================================================
// Kernel 1: C (M x 128) = A (M x 128) @ W (128 x 128), single fp16 mma.sync
// (fp32 accumulate) -> +b1 (cols<64) -> fp16 store.   [R8 known-good]
// CTA: BM=64, 256 threads = 8 warps (2x4), warp tile m32 x n32, full K=128.
// ===========================================================================
#define SM_AH 0
#define SM_WH 17408
#define SM_B1 52224
#define SMEM_GEMM_TOTAL (SM_B1 + 64 * 4)

__global__ __launch_bounds__(256, 3)
void precompute_kernel(const float* __restrict__ A,
                       const float* __restrict__ b1,
                       int M)
{
    extern __shared__ char smem[];
    const uint32_t sb  = smem_u32(smem);
    const int tid  = threadIdx.x;
    const int wid  = tid >> 5;
    const int lane = tid & 31;
    const int bm   = blockIdx.x * 64;

    // ---- W: flat async copy of the pre-built fp16 image (34,816 B) ----
    {
        const uint4* src = (const uint4*)g_W;
#pragma unroll
        for (int i = 0; i < 9; i++) {
            int v = tid + i * 256;               // 0..2303
            if (v < 2176) cp_async16(sb + SM_WH + v * 16, src + v);
        }
        asm volatile("cp.async.commit_group;" ::: "memory");
    }

    float* b1s = (float*)(smem + SM_B1);
    if (tid < 64) b1s[tid] = b1[tid];

    // ---- A tile: 64 rows x 128 cols f32 -> fp16 ----
#pragma unroll
    for (int i = 0; i < 8; i++) {
        int idx4 = tid + i * 256;                // 0..2047
        int row  = idx4 >> 5;                    // 0..63
        int col  = (idx4 & 31) * 4;              // 0..124
        int gr   = bm + row; if (gr >= M) gr = M - 1;
        float4 v = *(const float4*)(A + (size_t)gr * D_FEAT + col);
        uint32_t off = ((uint32_t)row * SA + col) * 2;
        *(uint32_t*)(smem + SM_AH + off)     = packh2(v.x, v.y);
        *(uint32_t*)(smem + SM_AH + off + 4) = packh2(v.z, v.w);
    }
    asm volatile("cp.async.wait_group 0;" ::: "memory");
    __syncthreads();

    // ---- Warp tiles: 2 (m) x 4 (n); each warp m32 x n32 ----
    const int wm = wid >> 2;            // 0..1
    const int wn = wid & 3;             // 0..3
    const int m_base = wm * 32;
    const int n_base = wn * 32;

    const int rA  = (lane & 7) + ((lane >> 3) & 1) * 8;
    const int kA8 = ((lane >> 4) & 1) * 8;
    const uint32_t aoff = ((uint32_t)(m_base + rA) * SA + kA8) * 2;
    const int rB  = lane & 7;
    const int kB8 = ((lane >> 3) & 1) * 8;
    const uint32_t boff = ((uint32_t)(n_base + rB) * SA + kB8) * 2;

    float acc[2][4][4];
#pragma unroll
    for (int mt = 0; mt < 2; mt++)
#pragma unroll
        for (int nt = 0; nt < 4; nt++)
#pragma unroll
            for (int r = 0; r < 4; r++) acc[mt][nt][r] = 0.f;

#pragma unroll
    for (int s = 0; s < 8; s++) {
        const uint32_t k0b = (uint32_t)(s * 16) * 2;
        uint32_t ah[2][4], bh[4][2];
#pragma unroll
        for (int mt = 0; mt < 2; mt++)
            ldsm_x4(ah[mt], sb + SM_AH + aoff + (uint32_t)(mt * 16 * SA) * 2 + k0b);
#pragma unroll
        for (int nt = 0; nt < 4; nt++)
            ldsm_x2(bh[nt], sb + SM_WH + boff + (uint32_t)(nt * 8 * SA) * 2 + k0b);
#pragma unroll
        for (int mt = 0; mt < 2; mt++)
#pragma unroll
            for (int nt = 0; nt < 4; nt++)
                mma_fp16(acc[mt][nt], ah[mt], bh[nt]);
    }

    // ---- Epilogue: +bias (cols<64), convert fp16, store half2 ----
    const int er = lane >> 2;
    const int ec = (lane & 3) * 2;
#pragma unroll
    for (int mt = 0; mt < 2; mt++) {
#pragma unroll
        for (int half = 0; half < 2; half++) {
            int gm = bm + m_base + mt * 16 + er + half * 8;
            if (gm >= M) continue;
            __half* dst = g_C + (size_t)gm * 128;
#pragma unroll
            for (int nt = 0; nt < 4; nt++) {
                int col = n_base + nt * 8 + ec;
                float x = acc[mt][nt][half * 2 + 0];
                float y = acc[mt][nt][half * 2 + 1];
                if (col < 64) { x += b1s[col]; y += b1s[col + 1]; }
                *(__half2*)(dst + col) = __floats2half2_rn(x, y);
            }
        }
    }
}

// ===========================================================================
// Kernel 2: per-edge readout, 8 threads/edge, 4 edges per thread-group
// (8 independent gathers in flight per thread).
// out[e] = sum_j relu(C[s][j] + C[d][64+j]) * w2[j]
// ===========================================================================
__global__ __launch_bounds__(256)
void edge_kernel(const unsigned int* __restrict__ ts_raw,
                 const float* __restrict__ w2,
                 float* __restrict__ out, int E, int M)
{
    __shared__ float w2s[HIDDEN];
    __shared__ int is64;
    if (threadIdx.x < HIDDEN) w2s[threadIdx.x] = w2[threadIdx.x];
    if (threadIdx.x == 0) {
        // int64 indices < 2^17 => every odd u32 word is 0 (little-endian)
        unsigned int acc = 0;
#pragma unroll
        for (int i = 1; i < 32; i += 2) acc |= ts_raw[i];
        is64 = (acc == 0) ? 1 : 0;
    }
    __syncthreads();

    const int tid = threadIdx.x;
    const int sub = tid & 7;
    const int grp = tid >> 3;                       // 0..31
    const int ebase = blockIdx.x * 128 + grp;       // edges ebase + 32*j

    unsigned int si[4], di[4];
#pragma unroll
    for (int j = 0; j < 4; j++) { si[j] = 0; di[j] = 0; }
    if (sub == 0) {
#pragma unroll
        for (int j = 0; j < 4; j++) {
            int e = ebase + 32 * j;
            unsigned int s = 0, d = 0;
            if (e < E) {
                if (is64) { s = ts_raw[4 * (size_t)e]; d = ts_raw[4 * (size_t)e + 2]; }
                else      { s = ts_raw[2 * (size_t)e]; d = ts_raw[2 * (size_t)e + 1]; }
            }
            if (s >= (unsigned)M) s = 0;
            if (d >= (unsigned)M) d = 0;
            si[j] = s; di[j] = d;
        }
    }
#pragma unroll
    for (int j = 0; j < 4; j++) {
        si[j] = __shfl_sync(0xffffffffu, si[j], 0, 8);
        di[j] = __shfl_sync(0xffffffffu, di[j], 0, 8);
    }

    // 8 independent 16B gathers in flight
    uint4 p[4], q[4];
#pragma unroll
    for (int j = 0; j < 4; j++) {
        p[j] = *((const uint4*)(g_C + (size_t)si[j] * 128) + sub);
        q[j] = *((const uint4*)(g_C + (size_t)di[j] * 128 + 64) + sub);
    }

    float4 w0 = ((const float4*)w2s)[sub * 2];
    float4 w1v = ((const float4*)w2s)[sub * 2 + 1];
    const float wv[8] = {w0.x, w0.y, w0.z, w0.w, w1v.x, w1v.y, w1v.z, w1v.w};

    float acc[4] = {0.f, 0.f, 0.f, 0.f};
#pragma unroll
    for (int j = 0; j < 4; j++) {
        const __half2* ph = (const __half2*)&p[j];
        const __half2* qh = (const __half2*)&q[j];
#pragma unroll
        for (int i = 0; i < 4; i++) {
            float2 a = __half22float2(ph[i]);
            float2 b = __half22float2(qh[i]);
            acc[j] = fmaf(fmaxf(a.x + b.x, 0.f), wv[i * 2 + 0], acc[j]);
            acc[j] = fmaf(fmaxf(a.y + b.y, 0.f), wv[i * 2 + 1], acc[j]);
        }
    }
#pragma unroll
    for (int off = 4; off >= 1; off >>= 1)
#pragma unroll
        for (int j = 0; j < 4; j++)
            acc[j] += __shfl_down_sync(0xffffffffu, acc[j], off, 8);

    if (sub == 0) {
#pragma unroll
        for (int j = 0; j < 4; j++) {
            int e = ebase + 32 * j;
            if (e < E) out[e] = acc[j];
        }
    }
}

// ===========================================================================
extern "C" void kernel_launch(void* const* d_in, const int* in_sizes, int n_in,
                              void* d_out, int out_size)
{
    const float*        emb = (const float*)d_in[0];
    const unsigned int* ts  = (const unsigned int*)d_in[1];
    const float*        w1  = (const float*)d_in[2];
    const float*        b1  = (const float*)d_in[3];
    const float*        w2  = (const float*)d_in[4];
    float*              out = (float*)d_out;

    int M = in_sizes[0] / D_FEAT;
    int E = in_sizes[1] / 2;

    setup_w_kernel<<<64, 256>>>(w1);
    cudaFuncSetAttribute(precompute_kernel,
                         cudaFuncAttributeMaxDynamicSharedMemorySize, SMEM_GEMM_TOTAL);
    precompute_kernel<<<(M + 63) / 64, 256, SMEM_GEMM_TOTAL>>>(emb, b1, M);
    edge_kernel<<<(E + 127) / 128, 256>>>(ts, w2, out, E, M);
}

// round 11
// speedup vs baseline: 4.1797x; 1.0577x over previous
#include <cuda_runtime.h>
#include <cuda_fp16.h>
#include <cstdint>
#include <cstddef>

#define N_NODES_MAX 100000
#define D_FEAT 128
#define HIDDEN 64
#define SA 136   // smem/global W row stride in fp16 units (272 B)

// fp16 node table: C[n][0:64] = emb@w1_top + b1 ; C[n][64:128] = emb@w1_bot
__device__ __align__(16) __half g_C[(size_t)N_NODES_MAX * 128];
// Pre-converted W (fp16), [128 n][SA k] — exact smem image
__device__ __align__(16) __half g_W[128 * SA];

// ===========================================================================
// PTX helpers (sm_80-era; compile under plain sm_100 target)
// ===========================================================================
__device__ __forceinline__ uint32_t smem_u32(const void* p) {
    uint32_t a;
    asm("{ .reg .u64 t; cvta.to.shared.u64 t, %1; cvt.u32.u64 %0, t; }"
        : "=r"(a) : "l"(p));
    return a;
}
__device__ __forceinline__ void ldsm_x4(uint32_t* r, uint32_t addr) {
    asm volatile("ldmatrix.sync.aligned.m8n8.x4.shared.b16 {%0,%1,%2,%3}, [%4];"
                 : "=r"(r[0]), "=r"(r[1]), "=r"(r[2]), "=r"(r[3]) : "r"(addr));
}
__device__ __forceinline__ void ldsm_x2(uint32_t* r, uint32_t addr) {
    asm volatile("ldmatrix.sync.aligned.m8n8.x2.shared.b16 {%0,%1}, [%2];"
                 : "=r"(r[0]), "=r"(r[1]) : "r"(addr));
}
__device__ __forceinline__ void mma_fp16(float* c, const uint32_t* a, const uint32_t* b) {
    asm volatile("mma.sync.aligned.m16n8k16.row.col.f32.f16.f16.f32 "
                 "{%0,%1,%2,%3}, {%4,%5,%6,%7}, {%8,%9}, {%0,%1,%2,%3};"
                 : "+f"(c[0]), "+f"(c[1]), "+f"(c[2]), "+f"(c[3])
                 : "r"(a[0]), "r"(a[1]), "r"(a[2]), "r"(a[3]),
                   "r"(b[0]), "r"(b[1]));
}
__device__ __forceinline__ void cp_async16(uint32_t dst, const void* src) {
    asm volatile("cp.async.cg.shared.global [%0], [%1], 16;"
                 :: "r"(dst), "l"(src) : "memory");
}
__device__ __forceinline__ uint32_t packh2(float x, float y) {
    __half2 t = __floats2half2_rn(x, y);
    return *(uint32_t*)&t;
}

// ===========================================================================
// Kernel 0: convert w1 -> g_W (fp16), layout [n][k], k contiguous.
//   W[n][k] = n<64 ? w1[k*64+n] : w1[(128+k)*64 + (n-64)]
// Each thread handles 2 adjacent k at one n -> one aligned 4-byte store;
// warp stores are 128 B contiguous (was: 2-byte stores striding 272 B).
// ===========================================================================
__global__ void setup_w_kernel(const float* __restrict__ w1)
{
    int idx = blockIdx.x * blockDim.x + threadIdx.x;   // 0..8191
    if (idx >= 128 * 64) return;
    int n  = idx >> 6;            // 0..127
    int k2 = (idx & 63) * 2;      // 0..126
    int base = (n < 64) ? 0 : 128;
    int nn   = (n < 64) ? n : (n - 64);
    float v0 = w1[(size_t)(base + k2)     * HIDDEN + nn];
    float v1 = w1[(size_t)(base + k2 + 1) * HIDDEN + nn];
    *(uint32_t*)&g_W[n * SA + k2] = packh2(v0, v1);
}

// ===========================================================================
// Kernel 1: C (M x 128) = A (M x 128) @ W (128 x 128), single fp16 mma.sync
// (fp32 accumulate) -> +b1 (cols<64) -> smem -> coalesced fp16 store.
// CTA: BM=64, 256 threads = 8 warps (2x4), warp tile m32 x n32, full K=128.
// ===========================================================================
#define SM_AH 0
#define SM_WH 17408
#define SM_B1 52224
#define SMEM_GEMM_TOTAL (SM_B1 + 64 * 4)

__global__ __launch_bounds__(256, 3)
void precompute_kernel(const float* __restrict__ A,
                       const float* __restrict__ b1,
                       int M)
{
    extern __shared__ char smem[];
    const uint32_t sb  = smem_u32(smem);
    const int tid  = threadIdx.x;
    const int wid  = tid >> 5;
    const int lane = tid & 31;
    const int bm   = blockIdx.x * 64;

    // ---- W: flat async copy of the pre-built fp16 image (34,816 B) ----
    {
        const uint4* src = (const uint4*)g_W;
#pragma unroll
        for (int i = 0; i < 9; i++) {
            int v = tid + i * 256;               // 0..2303
            if (v < 2176) cp_async16(sb + SM_WH + v * 16, src + v);
        }
        asm volatile("cp.async.commit_group;" ::: "memory");
    }

    float* b1s = (float*)(smem + SM_B1);
    if (tid < 64) b1s[tid] = b1[tid];

    // ---- A tile: 64 rows x 128 cols f32 -> fp16 ----
#pragma unroll
    for (int i = 0; i < 8; i++) {
        int idx4 = tid + i * 256;                // 0..2047
        int row  = idx4 >> 5;                    // 0..63
        int col  = (idx4 & 31) * 4;              // 0..124
        int gr   = bm + row; if (gr >= M) gr = M - 1;
        float4 v = *(const float4*)(A + (size_t)gr * D_FEAT + col);
        uint32_t off = ((uint32_t)row * SA + col) * 2;
        *(uint32_t*)(smem + SM_AH + off)     = packh2(v.x, v.y);
        *(uint32_t*)(smem + SM_AH + off + 4) = packh2(v.z, v.w);
    }
    asm volatile("cp.async.wait_group 0;" ::: "memory");
    __syncthreads();

    // ---- Warp tiles: 2 (m) x 4 (n); each warp m32 x n32 ----
    const int wm = wid >> 2;            // 0..1
    const int wn = wid & 3;             // 0..3
    const int m_base = wm * 32;
    const int n_base = wn * 32;

    const int rA  = (lane & 7) + ((lane >> 3) & 1) * 8;
    const int kA8 = ((lane >> 4) & 1) * 8;
    const uint32_t aoff = ((uint32_t)(m_base + rA) * SA + kA8) * 2;
    const int rB  = lane & 7;
    const int kB8 = ((lane >> 3) & 1) * 8;
    const uint32_t boff = ((uint32_t)(n_base + rB) * SA + kB8) * 2;

    float acc[2][4][4];
#pragma unroll
    for (int mt = 0; mt < 2; mt++)
#pragma unroll
        for (int nt = 0; nt < 4; nt++)
#pragma unroll
            for (int r = 0; r < 4; r++) acc[mt][nt][r] = 0.f;

#pragma unroll
    for (int s = 0; s < 8; s++) {
        const uint32_t k0b = (uint32_t)(s * 16) * 2;
        uint32_t ah[2][4], bh[4][2];
#pragma unroll
        for (int mt = 0; mt < 2; mt++)
            ldsm_x4(ah[mt], sb + SM_AH + aoff + (uint32_t)(mt * 16 * SA) * 2 + k0b);
#pragma unroll
        for (int nt = 0; nt < 4; nt++)
            ldsm_x2(bh[nt], sb + SM_WH + boff + (uint32_t)(nt * 8 * SA) * 2 + k0b);
#pragma unroll
        for (int mt = 0; mt < 2; mt++)
#pragma unroll
            for (int nt = 0; nt < 4; nt++)
                mma_fp16(acc[mt][nt], ah[mt], bh[nt]);
    }

    // ---- Epilogue pass 1: +bias, fp16, STS into the A buffer (conflict-free:
    //      bank = (er*68 + ec/2) % 32 = er*4 + ec/2, all 32 lanes distinct) ----
    __syncthreads();   // all warps done reading SM_AH via ldmatrix
    const int er = lane >> 2;
    const int ec = (lane & 3) * 2;
#pragma unroll
    for (int mt = 0; mt < 2; mt++) {
#pragma unroll
        for (int half = 0; half < 2; half++) {
            int lrow = m_base + mt * 16 + er + half * 8;   // 0..63
#pragma unroll
            for (int nt = 0; nt < 4; nt++) {
                int col = n_base + nt * 8 + ec;
                float x = acc[mt][nt][half * 2 + 0];
                float y = acc[mt][nt][half * 2 + 1];
                if (col < 64) { x += b1s[col]; y += b1s[col + 1]; }
                *(uint32_t*)(smem + SM_AH + ((uint32_t)lrow * SA + col) * 2) = packh2(x, y);
            }
        }
    }
    __syncthreads();

    // ---- Epilogue pass 2: coalesced STG.128 (2 rows x 256 B per warp-store) ----
#pragma unroll
    for (int i = 0; i < 4; i++) {
        int v   = tid + i * 256;         // 0..1023
        int row = v >> 4;                // 0..63
        int c16 = v & 15;                // 16 uint4 per 128-half row
        int gm  = bm + row;
        if (gm < M) {
            *(uint4*)(g_C + (size_t)gm * 128 + c16 * 8) =
                *(const uint4*)(smem + SM_AH + ((uint32_t)row * SA + c16 * 8) * 2);
        }
    }
}

// ===========================================================================
// Kernel 2: per-edge readout, 8 threads/edge, 4 edges per thread-group.
// out[e] = sum_j relu(C[s][j] + C[d][64+j]) * w2[j]
// ===========================================================================
__global__ __launch_bounds__(256)
void edge_kernel(const unsigned int* __restrict__ ts_raw,
                 const float* __restrict__ w2,
                 float* __restrict__ out, int E, int M)
{
    __shared__ float w2s[HIDDEN];
    __shared__ int is64;
    if (threadIdx.x < HIDDEN) w2s[threadIdx.x] = w2[threadIdx.x];
    if (threadIdx.x == 0) {
        // int64 indices < 2^17 => every odd u32 word is 0 (little-endian)
        unsigned int acc = 0;
#pragma unroll
        for (int i = 1; i < 32; i += 2) acc |= ts_raw[i];
        is64 = (acc == 0) ? 1 : 0;
    }
    __syncthreads();

    const int tid = threadIdx.x;
    const int sub = tid & 7;
    const int grp = tid >> 3;                       // 0..31
    const int ebase = blockIdx.x * 128 + grp;       // edges ebase + 32*j

    unsigned int si[4], di[4];
#pragma unroll
    for (int j = 0; j < 4; j++) { si[j] = 0; di[j] = 0; }
    if (sub == 0) {
#pragma unroll
        for (int j = 0; j < 4; j++) {
            int e = ebase + 32 * j;
            unsigned int s = 0, d = 0;
            if (e < E) {
                if (is64) { s = ts_raw[4 * (size_t)e]; d = ts_raw[4 * (size_t)e + 2]; }
                else      { s = ts_raw[2 * (size_t)e]; d = ts_raw[2 * (size_t)e + 1]; }
            }
            if (s >= (unsigned)M) s = 0;
            if (d >= (unsigned)M) d = 0;
            si[j] = s; di[j] = d;
        }
    }
#pragma unroll
    for (int j = 0; j < 4; j++) {
        si[j] = __shfl_sync(0xffffffffu, si[j], 0, 8);
        di[j] = __shfl_sync(0xffffffffu, di[j], 0, 8);
    }

    // 8 independent 16B gathers in flight
    uint4 p[4], q[4];
#pragma unroll
    for (int j = 0; j < 4; j++) {
        p[j] = *((const uint4*)(g_C + (size_t)si[j] * 128) + sub);
        q[j] = *((const uint4*)(g_C + (size_t)di[j] * 128 + 64) + sub);
    }

    float4 w0 = ((const float4*)w2s)[sub * 2];
    float4 w1v = ((const float4*)w2s)[sub * 2 + 1];
    const float wv[8] = {w0.x, w0.y, w0.z, w0.w, w1v.x, w1v.y, w1v.z, w1v.w};

    float acc[4] = {0.f, 0.f, 0.f, 0.f};
#pragma unroll
    for (int j = 0; j < 4; j++) {
        const __half2* ph = (const __half2*)&p[j];
        const __half2* qh = (const __half2*)&q[j];
#pragma unroll
        for (int i = 0; i < 4; i++) {
            float2 a = __half22float2(ph[i]);
            float2 b = __half22float2(qh[i]);
            acc[j] = fmaf(fmaxf(a.x + b.x, 0.f), wv[i * 2 + 0], acc[j]);
            acc[j] = fmaf(fmaxf(a.y + b.y, 0.f), wv[i * 2 + 1], acc[j]);
        }
    }
#pragma unroll
    for (int off = 4; off >= 1; off >>= 1)
#pragma unroll
        for (int j = 0; j < 4; j++)
            acc[j] += __shfl_down_sync(0xffffffffu, acc[j], off, 8);

    if (sub == 0) {
#pragma unroll
        for (int j = 0; j < 4; j++) {
            int e = ebase + 32 * j;
            if (e < E) out[e] = acc[j];
        }
    }
}

// ===========================================================================
extern "C" void kernel_launch(void* const* d_in, const int* in_sizes, int n_in,
                              void* d_out, int out_size)
{
    const float*        emb = (const float*)d_in[0];
    const unsigned int* ts  = (const unsigned int*)d_in[1];
    const float*        w1  = (const float*)d_in[2];
    const float*        b1  = (const float*)d_in[3];
    const float*        w2  = (const float*)d_in[4];
    float*              out = (float*)d_out;

    int M = in_sizes[0] / D_FEAT;
    int E = in_sizes[1] / 2;

    setup_w_kernel<<<32, 256>>>(w1);
    cudaFuncSetAttribute(precompute_kernel,
                         cudaFuncAttributeMaxDynamicSharedMemorySize, SMEM_GEMM_TOTAL);
    precompute_kernel<<<(M + 63) / 64, 256, SMEM_GEMM_TOTAL>>>(emb, b1, M);
    edge_kernel<<<(E + 127) / 128, 256>>>(ts, w2, out, E, M);
}